// round 2
// baseline (speedup 1.0000x reference)
#include <cuda_runtime.h>
#include <math.h>

// ---------------------------------------------------------------------------
// BiomechanicsLoss: W = sqrt( sum_{i: sdf_i < 1e-8} q_i^2 ) / count
//   q_i = et_i^T C et_i,  et = [ux, vy, wz, .5(uy+vx), .5(uz+wx), .5(wy+vz)]
// C = inv(Ci), Ci block-diagonal (asymmetric 3x3 block + diag shear block).
// Pure streaming reduction: 160 MB in -> 4 B out. HBM-bound.
// ---------------------------------------------------------------------------

struct CMat {
    float m[9];  // 3x3 normal-strain block of C (row-major), NOT symmetric
    float s;     // shear diagonal C[3][3] == C[4][4] == C[5][5]
};

__device__ double             g_sum;     // zero-initialized; reset by last block
__device__ unsigned long long g_cnt;
__device__ unsigned int       g_ticket;

__global__ void __launch_bounds__(256)
biomech_loss_kernel(const float* __restrict__ gu,
                    const float* __restrict__ gv,
                    const float* __restrict__ gw,
                    const float* __restrict__ sdf,
                    float* __restrict__ out,
                    int npts, CMat C, unsigned int nblocks)
{
    const int tid = blockIdx.x * blockDim.x + threadIdx.x;
    const long long base = (long long)tid * 4;

    float lsum = 0.0f;
    int   lcnt = 0;

    if (base + 4 <= (long long)npts) {
        // Vector path: 4 points = 3 float4 per gradient array + 1 float4 sdf.
        const float4* u4 = reinterpret_cast<const float4*>(gu) + 3 * tid;
        const float4* v4 = reinterpret_cast<const float4*>(gv) + 3 * tid;
        const float4* w4 = reinterpret_cast<const float4*>(gw) + 3 * tid;

        float4 ua0 = u4[0], ua1 = u4[1], ua2 = u4[2];
        float4 va0 = v4[0], va1 = v4[1], va2 = v4[2];
        float4 wa0 = w4[0], wa1 = w4[1], wa2 = w4[2];
        float4 sv  = reinterpret_cast<const float4*>(sdf)[tid];

        float ue[12], ve[12], we[12], se[4];
        *reinterpret_cast<float4*>(&ue[0]) = ua0;
        *reinterpret_cast<float4*>(&ue[4]) = ua1;
        *reinterpret_cast<float4*>(&ue[8]) = ua2;
        *reinterpret_cast<float4*>(&ve[0]) = va0;
        *reinterpret_cast<float4*>(&ve[4]) = va1;
        *reinterpret_cast<float4*>(&ve[8]) = va2;
        *reinterpret_cast<float4*>(&we[0]) = wa0;
        *reinterpret_cast<float4*>(&we[4]) = wa1;
        *reinterpret_cast<float4*>(&we[8]) = wa2;
        *reinterpret_cast<float4*>(&se[0]) = sv;

        #pragma unroll
        for (int k = 0; k < 4; k++) {
            float ux = ue[3*k+0], uy = ue[3*k+1], uz = ue[3*k+2];
            float vx = ve[3*k+0], vy = ve[3*k+1], vz = ve[3*k+2];
            float wx = we[3*k+0], wy = we[3*k+1], wz = we[3*k+2];

            float e0 = ux, e1 = vy, e2 = wz;
            float e3 = 0.5f * (uy + vx);
            float e4 = 0.5f * (uz + wx);
            float e5 = 0.5f * (wy + vz);

            float q = e0 * (C.m[0]*e0 + C.m[1]*e1 + C.m[2]*e2)
                    + e1 * (C.m[3]*e0 + C.m[4]*e1 + C.m[5]*e2)
                    + e2 * (C.m[6]*e0 + C.m[7]*e1 + C.m[8]*e2)
                    + C.s * (e3*e3 + e4*e4 + e5*e5);

            if (se[k] < 1e-8f) { lsum += q * q; lcnt += 1; }
        }
    } else if (base < (long long)npts) {
        // Scalar tail (only if npts % 4 != 0; not hit for N = 4M).
        for (long long p = base; p < (long long)npts; p++) {
            float ux = gu[3*p+0], uy = gu[3*p+1], uz = gu[3*p+2];
            float vx = gv[3*p+0], vy = gv[3*p+1], vz = gv[3*p+2];
            float wx = gw[3*p+0], wy = gw[3*p+1], wz = gw[3*p+2];

            float e0 = ux, e1 = vy, e2 = wz;
            float e3 = 0.5f * (uy + vx);
            float e4 = 0.5f * (uz + wx);
            float e5 = 0.5f * (wy + vz);

            float q = e0 * (C.m[0]*e0 + C.m[1]*e1 + C.m[2]*e2)
                    + e1 * (C.m[3]*e0 + C.m[4]*e1 + C.m[5]*e2)
                    + e2 * (C.m[6]*e0 + C.m[7]*e1 + C.m[8]*e2)
                    + C.s * (e3*e3 + e4*e4 + e5*e5);

            if (sdf[p] < 1e-8f) { lsum += q * q; lcnt += 1; }
        }
    }

    // ---- warp reduce ----
    #pragma unroll
    for (int off = 16; off > 0; off >>= 1) {
        lsum += __shfl_down_sync(0xffffffffu, lsum, off);
        lcnt += __shfl_down_sync(0xffffffffu, lcnt, off);
    }

    // ---- block reduce across 8 warps ----
    __shared__ float ssum[8];
    __shared__ int   scnt[8];
    const int lane = threadIdx.x & 31;
    const int wid  = threadIdx.x >> 5;
    if (lane == 0) { ssum[wid] = lsum; scnt[wid] = lcnt; }
    __syncthreads();

    if (wid == 0) {
        lsum = (lane < 8) ? ssum[lane] : 0.0f;
        lcnt = (lane < 8) ? scnt[lane] : 0;
        #pragma unroll
        for (int off = 4; off > 0; off >>= 1) {
            lsum += __shfl_down_sync(0xffffffffu, lsum, off);
            lcnt += __shfl_down_sync(0xffffffffu, lcnt, off);
        }
        if (lane == 0) {
            atomicAdd(&g_sum, (double)lsum);
            atomicAdd(&g_cnt, (unsigned long long)lcnt);
            __threadfence();
            unsigned int t = atomicAdd(&g_ticket, 1u);
            if (t == nblocks - 1u) {
                // All blocks' contributions are visible (atomic+fence chain).
                double s = __longlong_as_double(
                    atomicExch((unsigned long long*)&g_sum, 0ULL));
                unsigned long long c = atomicExch(&g_cnt, 0ULL);
                out[0] = (float)(sqrt(s) / (double)c);
                atomicExch(&g_ticket, 0u);  // reset for next graph replay
            }
        }
    }
}

// ---------------------------------------------------------------------------
// Host side: build Ci exactly as the reference (including the asymmetry),
// invert in double via Gauss-Jordan, cast to float.
// ---------------------------------------------------------------------------
static void build_C(CMat* out)
{
    const double vp = 0.4, Ep = 0.21;
    double Ci[6][6] = {};
    Ci[0][0] = 1.0 / Ep;  Ci[0][1] = -vp / Ep; Ci[0][2] = -vp / Ep;
    Ci[1][0] = -vp / Ep;  Ci[1][1] = 1.0 / Ep; Ci[1][2] = -vp / Ep;
    Ci[2][0] = -vp;       Ci[2][1] = -vp;      Ci[2][2] = 1.0 / Ep;
    Ci[3][3] = 2.0 * (1.0 + vp) / Ep;
    Ci[4][4] = 2.0 * (1.0 + vp) / Ep;
    Ci[5][5] = 2.0 * (1.0 + vp) / Ep;

    // Gauss-Jordan with partial pivoting on [Ci | I]
    double M[6][12];
    for (int i = 0; i < 6; i++)
        for (int j = 0; j < 6; j++) {
            M[i][j]     = Ci[i][j];
            M[i][6 + j] = (i == j) ? 1.0 : 0.0;
        }
    for (int col = 0; col < 6; col++) {
        int p = col;
        for (int r = col + 1; r < 6; r++)
            if (fabs(M[r][col]) > fabs(M[p][col])) p = r;
        if (p != col)
            for (int j = 0; j < 12; j++) {
                double tmp = M[col][j]; M[col][j] = M[p][j]; M[p][j] = tmp;
            }
        double d = M[col][col];
        for (int j = 0; j < 12; j++) M[col][j] /= d;
        for (int r = 0; r < 6; r++) {
            if (r == col) continue;
            double f = M[r][col];
            if (f == 0.0) continue;
            for (int j = 0; j < 12; j++) M[r][j] -= f * M[col][j];
        }
    }

    for (int i = 0; i < 3; i++)
        for (int j = 0; j < 3; j++)
            out->m[i * 3 + j] = (float)M[i][6 + j];
    out->s = (float)M[3][6 + 3];
}

extern "C" void kernel_launch(void* const* d_in, const int* in_sizes, int n_in,
                              void* d_out, int out_size)
{
    (void)n_in; (void)out_size;
    const float* gu  = (const float*)d_in[0];
    const float* gv  = (const float*)d_in[1];
    const float* gw  = (const float*)d_in[2];
    const float* sdf = (const float*)d_in[3];
    float* out = (float*)d_out;

    const int npts = in_sizes[3];  // gt_sdf element count == N

    CMat C;
    build_C(&C);

    const int quads   = (npts + 3) / 4;           // points per thread = 4
    const int threads = 256;
    const unsigned int blocks = (unsigned int)((quads + threads - 1) / threads);

    biomech_loss_kernel<<<blocks, threads>>>(gu, gv, gw, sdf, out,
                                             npts, C, blocks);
}

// round 3
// speedup vs baseline: 1.0781x; 1.0781x over previous
#include <cuda_runtime.h>
#include <math.h>
#include <stdint.h>

// ---------------------------------------------------------------------------
// BiomechanicsLoss: W = sqrt( sum_{i: sdf_i < 1e-8} q_i^2 ) / count
//   q_i = et_i^T C et_i,  et = [ux, vy, wz, .5(uy+vx), .5(uz+wx), .5(wy+vz)]
// Streaming reduction, 160 MB -> 4 B. Strategy: persistent blocks +
// cp.async.bulk (TMA-class) double-buffered SMEM staging to saturate HBM.
// ---------------------------------------------------------------------------

#define TILE_PTS    1024
#define THREADS     256
#define PPT         4                       // points per thread per tile
#define GU_FLOATS   (TILE_PTS * 3)          // 3072
#define STAGE_FLOATS (GU_FLOATS * 3 + TILE_PTS)  // 10240 floats = 40960 B
#define STAGE_BYTES (STAGE_FLOATS * 4)
#define GRAD_BYTES  (GU_FLOATS * 4)         // 12288
#define SDF_BYTES   (TILE_PTS * 4)          // 4096

struct CMat {
    float m[9];  // asymmetric 3x3 normal-strain block of C, row-major
    float s;     // shear diagonal C[3][3] == C[4][4] == C[5][5]
};

__device__ double             g_sum;
__device__ unsigned long long g_cnt;
__device__ unsigned int       g_ticket;

// ---- PTX helpers ----------------------------------------------------------
__device__ __forceinline__ uint32_t smem_u32(const void* p) {
    return (uint32_t)__cvta_generic_to_shared(p);
}

__device__ __forceinline__ void mbar_init(uint32_t mbar, uint32_t count) {
    asm volatile("mbarrier.init.shared.b64 [%0], %1;" :: "r"(mbar), "r"(count) : "memory");
}

__device__ __forceinline__ void mbar_expect_tx(uint32_t mbar, uint32_t bytes) {
    asm volatile("mbarrier.arrive.expect_tx.shared.b64 _, [%0], %1;"
                 :: "r"(mbar), "r"(bytes) : "memory");
}

__device__ __forceinline__ void mbar_wait(uint32_t mbar, uint32_t parity) {
    asm volatile(
        "{\n\t"
        ".reg .pred P;\n\t"
        "WAIT_%=:\n\t"
        "mbarrier.try_wait.parity.acquire.cta.shared::cta.b64 P, [%0], %1, 0x989680;\n\t"
        "@P bra DONE_%=;\n\t"
        "bra WAIT_%=;\n\t"
        "DONE_%=:\n\t"
        "}"
        :: "r"(mbar), "r"(parity) : "memory");
}

__device__ __forceinline__ void bulk_copy_g2s(uint32_t dst_smem, const void* src_gmem,
                                              uint32_t bytes, uint32_t mbar) {
    asm volatile(
        "cp.async.bulk.shared::cta.global.mbarrier::complete_tx::bytes "
        "[%0], [%1], %2, [%3];"
        :: "r"(dst_smem), "l"(src_gmem), "r"(bytes), "r"(mbar) : "memory");
}

// ---- quadratic form on 4 points held in float4 triplets -------------------
__device__ __forceinline__ void accum4(const float4& ua0, const float4& ua1, const float4& ua2,
                                       const float4& va0, const float4& va1, const float4& va2,
                                       const float4& wa0, const float4& wa1, const float4& wa2,
                                       const float4& sv, const CMat& C,
                                       float& lsum, int& lcnt)
{
    float ue[12], ve[12], we[12], se[4];
    *reinterpret_cast<float4*>(&ue[0]) = ua0;
    *reinterpret_cast<float4*>(&ue[4]) = ua1;
    *reinterpret_cast<float4*>(&ue[8]) = ua2;
    *reinterpret_cast<float4*>(&ve[0]) = va0;
    *reinterpret_cast<float4*>(&ve[4]) = va1;
    *reinterpret_cast<float4*>(&ve[8]) = va2;
    *reinterpret_cast<float4*>(&we[0]) = wa0;
    *reinterpret_cast<float4*>(&we[4]) = wa1;
    *reinterpret_cast<float4*>(&we[8]) = wa2;
    *reinterpret_cast<float4*>(&se[0]) = sv;

    #pragma unroll
    for (int k = 0; k < 4; k++) {
        float ux = ue[3*k+0], uy = ue[3*k+1], uz = ue[3*k+2];
        float vx = ve[3*k+0], vy = ve[3*k+1], vz = ve[3*k+2];
        float wx = we[3*k+0], wy = we[3*k+1], wz = we[3*k+2];

        float e0 = ux, e1 = vy, e2 = wz;
        float e3 = 0.5f * (uy + vx);
        float e4 = 0.5f * (uz + wx);
        float e5 = 0.5f * (wy + vz);

        float q = e0 * (C.m[0]*e0 + C.m[1]*e1 + C.m[2]*e2)
                + e1 * (C.m[3]*e0 + C.m[4]*e1 + C.m[5]*e2)
                + e2 * (C.m[6]*e0 + C.m[7]*e1 + C.m[8]*e2)
                + C.s * (e3*e3 + e4*e4 + e5*e5);

        if (se[k] < 1e-8f) { lsum += q * q; lcnt += 1; }
    }
}

// ---------------------------------------------------------------------------
__global__ void __launch_bounds__(THREADS)
biomech_loss_tma(const float* __restrict__ gu,
                 const float* __restrict__ gv,
                 const float* __restrict__ gw,
                 const float* __restrict__ sdf,
                 float* __restrict__ out,
                 int npts, int ntiles, CMat C)
{
    extern __shared__ __align__(16) float smem[];
    __shared__ __align__(8) unsigned long long mbar_store[2];

    const int tid = threadIdx.x;
    const uint32_t mbar0 = smem_u32(&mbar_store[0]);
    const uint32_t mbar1 = smem_u32(&mbar_store[1]);

    if (tid == 0) {
        mbar_init(mbar0, 1);
        mbar_init(mbar1, 1);
    }
    __syncthreads();

    float lsum = 0.0f;
    int   lcnt = 0;

    const int stride = gridDim.x;

    // Issue helper (thread 0 only): stage s <- tile t
    auto issue = [&](int t, int s) {
        const uint32_t mbar = (s == 0) ? mbar0 : mbar1;
        const uint32_t base = smem_u32(smem) + (uint32_t)s * STAGE_BYTES;
        mbar_expect_tx(mbar, STAGE_BYTES);
        const size_t goff = (size_t)t * GU_FLOATS;   // floats into each grad array
        bulk_copy_g2s(base,                    gu + goff,               GRAD_BYTES, mbar);
        bulk_copy_g2s(base + GRAD_BYTES,       gv + goff,               GRAD_BYTES, mbar);
        bulk_copy_g2s(base + 2*GRAD_BYTES,     gw + goff,               GRAD_BYTES, mbar);
        bulk_copy_g2s(base + 3*GRAD_BYTES,     sdf + (size_t)t*TILE_PTS, SDF_BYTES, mbar);
    };

    // Prologue: issue first tile
    int t0 = blockIdx.x;
    if (t0 < ntiles && tid == 0) issue(t0, 0);

    int it = 0;
    for (int t = t0; t < ntiles; t += stride, it++) {
        const int s = it & 1;

        // Issue next tile into the other buffer (already consumed at it-1).
        const int tn = t + stride;
        if (tn < ntiles && tid == 0) issue(tn, s ^ 1);

        // Wait for this tile's data.
        mbar_wait((s == 0) ? mbar0 : mbar1, (it >> 1) & 1);

        // Consume: thread handles 4 consecutive points. Quarter-warp LDS.128
        // phases are bank-conflict-free at 48B stride.
        const float* stage = smem + (size_t)s * STAGE_FLOATS;
        const float4* u4 = reinterpret_cast<const float4*>(stage) + 3 * tid;
        const float4* v4 = reinterpret_cast<const float4*>(stage + GU_FLOATS) + 3 * tid;
        const float4* w4 = reinterpret_cast<const float4*>(stage + 2 * GU_FLOATS) + 3 * tid;
        const float4  sv = reinterpret_cast<const float4*>(stage + 3 * GU_FLOATS)[tid];

        accum4(u4[0], u4[1], u4[2],
               v4[0], v4[1], v4[2],
               w4[0], w4[1], w4[2],
               sv, C, lsum, lcnt);

        // All threads must finish reading stage s before it is refilled at it+2.
        __syncthreads();
    }

    // Remainder points (npts % TILE_PTS), handled by block 0 via global loads.
    if (blockIdx.x == 0) {
        for (int p = ntiles * TILE_PTS + tid; p < npts; p += THREADS) {
            float ux = gu[3*p+0], uy = gu[3*p+1], uz = gu[3*p+2];
            float vx = gv[3*p+0], vy = gv[3*p+1], vz = gv[3*p+2];
            float wx = gw[3*p+0], wy = gw[3*p+1], wz = gw[3*p+2];
            float e0 = ux, e1 = vy, e2 = wz;
            float e3 = 0.5f * (uy + vx);
            float e4 = 0.5f * (uz + wx);
            float e5 = 0.5f * (wy + vz);
            float q = e0 * (C.m[0]*e0 + C.m[1]*e1 + C.m[2]*e2)
                    + e1 * (C.m[3]*e0 + C.m[4]*e1 + C.m[5]*e2)
                    + e2 * (C.m[6]*e0 + C.m[7]*e1 + C.m[8]*e2)
                    + C.s * (e3*e3 + e4*e4 + e5*e5);
            if (sdf[p] < 1e-8f) { lsum += q * q; lcnt += 1; }
        }
    }

    // ---- warp reduce ----
    #pragma unroll
    for (int off = 16; off > 0; off >>= 1) {
        lsum += __shfl_down_sync(0xffffffffu, lsum, off);
        lcnt += __shfl_down_sync(0xffffffffu, lcnt, off);
    }

    // ---- block reduce across 8 warps ----
    __shared__ float ssum[8];
    __shared__ int   scnt[8];
    const int lane = threadIdx.x & 31;
    const int wid  = threadIdx.x >> 5;
    if (lane == 0) { ssum[wid] = lsum; scnt[wid] = lcnt; }
    __syncthreads();

    if (wid == 0) {
        lsum = (lane < 8) ? ssum[lane] : 0.0f;
        lcnt = (lane < 8) ? scnt[lane] : 0;
        #pragma unroll
        for (int off = 4; off > 0; off >>= 1) {
            lsum += __shfl_down_sync(0xffffffffu, lsum, off);
            lcnt += __shfl_down_sync(0xffffffffu, lcnt, off);
        }
        if (lane == 0) {
            atomicAdd(&g_sum, (double)lsum);
            atomicAdd(&g_cnt, (unsigned long long)lcnt);
            __threadfence();
            unsigned int t = atomicAdd(&g_ticket, 1u);
            if (t == gridDim.x - 1u) {
                double s = __longlong_as_double(
                    atomicExch((unsigned long long*)&g_sum, 0ULL));
                unsigned long long c = atomicExch(&g_cnt, 0ULL);
                out[0] = (float)(sqrt(s) / (double)c);
                atomicExch(&g_ticket, 0u);  // reset for next graph replay
            }
        }
    }
}

// ---------------------------------------------------------------------------
// Host: build Ci exactly as the reference (incl. asymmetry), invert in double.
// ---------------------------------------------------------------------------
static void build_C(CMat* out)
{
    const double vp = 0.4, Ep = 0.21;
    double Ci[6][6] = {};
    Ci[0][0] = 1.0 / Ep;  Ci[0][1] = -vp / Ep; Ci[0][2] = -vp / Ep;
    Ci[1][0] = -vp / Ep;  Ci[1][1] = 1.0 / Ep; Ci[1][2] = -vp / Ep;
    Ci[2][0] = -vp;       Ci[2][1] = -vp;      Ci[2][2] = 1.0 / Ep;
    Ci[3][3] = 2.0 * (1.0 + vp) / Ep;
    Ci[4][4] = 2.0 * (1.0 + vp) / Ep;
    Ci[5][5] = 2.0 * (1.0 + vp) / Ep;

    double M[6][12];
    for (int i = 0; i < 6; i++)
        for (int j = 0; j < 6; j++) {
            M[i][j]     = Ci[i][j];
            M[i][6 + j] = (i == j) ? 1.0 : 0.0;
        }
    for (int col = 0; col < 6; col++) {
        int p = col;
        for (int r = col + 1; r < 6; r++)
            if (fabs(M[r][col]) > fabs(M[p][col])) p = r;
        if (p != col)
            for (int j = 0; j < 12; j++) {
                double tmp = M[col][j]; M[col][j] = M[p][j]; M[p][j] = tmp;
            }
        double d = M[col][col];
        for (int j = 0; j < 12; j++) M[col][j] /= d;
        for (int r = 0; r < 6; r++) {
            if (r == col) continue;
            double f = M[r][col];
            if (f == 0.0) continue;
            for (int j = 0; j < 12; j++) M[r][j] -= f * M[col][j];
        }
    }

    for (int i = 0; i < 3; i++)
        for (int j = 0; j < 3; j++)
            out->m[i * 3 + j] = (float)M[i][6 + j];
    out->s = (float)M[3][6 + 3];
}

extern "C" void kernel_launch(void* const* d_in, const int* in_sizes, int n_in,
                              void* d_out, int out_size)
{
    (void)n_in; (void)out_size;
    const float* gu  = (const float*)d_in[0];
    const float* gv  = (const float*)d_in[1];
    const float* gw  = (const float*)d_in[2];
    const float* sdf = (const float*)d_in[3];
    float* out = (float*)d_out;

    const int npts   = in_sizes[3];            // gt_sdf count == N
    const int ntiles = npts / TILE_PTS;

    CMat C;
    build_C(&C);

    static int nsm = 0;
    if (nsm == 0) {
        cudaDeviceGetAttribute(&nsm, cudaDevAttrMultiProcessorCount, 0);
        if (nsm <= 0) nsm = 148;
    }
    int blocks = 2 * nsm;                      // 2 blocks/SM (80KB smem each)
    if (blocks < 1) blocks = 1;

    const int smem_bytes = 2 * STAGE_BYTES;    // double buffer: 81920 B
    cudaFuncSetAttribute(biomech_loss_tma,
                         cudaFuncAttributeMaxDynamicSharedMemorySize, smem_bytes);

    biomech_loss_tma<<<blocks, THREADS, smem_bytes>>>(gu, gv, gw, sdf, out,
                                                      npts, ntiles, C);
}